// round 10
// baseline (speedup 1.0000x reference)
#include <cuda_runtime.h>
#include <math_constants.h>

// Shapes fixed by the problem
#define B_  32
#define T_  12
#define N_  512
#define F_  64
#define H_  64

#define BLOCKS 256
#define THREADS 256
#define WARPS   8
#define PAIRS_PER_WARP  8      // 256 * 8 * 8 = 16384 = B*N
#define PAIRS_PER_BLOCK 64
#define NSU (PAIRS_PER_WARP / 2)   // 4 super-iters, 2 pairs each

// Per-block partial 12x12 gram matrices (overwritten every launch; no zeroing needed)
__device__ float g_partial[BLOCKS * 144];
// Ticket: zero at module load; last block resets to 0 each launch -> every
// graph replay starts clean (deterministic).
__device__ unsigned int g_ticket;

__global__ __launch_bounds__(THREADS) void fft_sel_fused(
    const float* __restrict__ x,   // [B,T,N,F]
    const float* __restrict__ Wq,  // [F,H]
    const float* __restrict__ bq,  // [H]
    const float* __restrict__ Wk,  // [F,H]
    const float* __restrict__ bk,  // [H]
    float* __restrict__ out, int out_n)
{
    __shared__ float s_wq[F_], s_wk[F_];
    __shared__ float s_bsum[2];
    __shared__ float s_q[PAIRS_PER_BLOCK * T_];   // 64 pairs x 12 t
    __shared__ float s_k[PAIRS_PER_BLOCK * T_];
    __shared__ float s_part[7][144];
    __shared__ float s_score[144];
    __shared__ bool  s_last;

    const int tid  = threadIdx.x;
    const int wid  = tid >> 5;
    const int lane = tid & 31;

    // ---- Coalesced pre-sum of weights over H (exact FFT/irfft/mean-H collapse) ----
    {
#pragma unroll
        for (int r = 0; r < 8; r++) {
            const int f = wid * 8 + r;
            float aq = Wq[f * H_ + lane] + Wq[f * H_ + 32 + lane];
            float ak = Wk[f * H_ + lane] + Wk[f * H_ + 32 + lane];
#pragma unroll
            for (int s = 16; s >= 1; s >>= 1) {
                aq += __shfl_xor_sync(0xffffffffu, aq, s);
                ak += __shfl_xor_sync(0xffffffffu, ak, s);
            }
            if (lane == 0) { s_wq[f] = aq; s_wk[f] = ak; }
        }
        if (wid == 0) {
            float a = bq[lane] + bq[32 + lane];
#pragma unroll
            for (int s = 16; s >= 1; s >>= 1) a += __shfl_xor_sync(0xffffffffu, a, s);
            if (lane == 0) s_bsum[0] = a;
        } else if (wid == 1) {
            float a = bk[lane] + bk[32 + lane];
#pragma unroll
            for (int s = 16; s >= 1; s >>= 1) a += __shfl_xor_sync(0xffffffffu, a, s);
            if (lane == 0) s_bsum[1] = a;
        }
    }
    __syncthreads();

    // ---- 4-lane-group streaming, software-pipelined (double-buffered) ----
    // Warp = 8 groups of 4 lanes. Per super-iter (2 pairs = 24 slots) each
    // group handles 3 slots; lane q loads interleaved float4s q,q+4,q+8,q+12.
    // Next su's 12 loads are issued BEFORE reducing the current su, so >=12
    // LDG.128 stay in flight per lane continuously.
    const int g = lane >> 2;
    const int q = lane & 3;

    float4 wq4r[4], wk4r[4];
#pragma unroll
    for (int i = 0; i < 4; i++) {
        wq4r[i] = ((const float4*)s_wq)[q + 4 * i];
        wk4r[i] = ((const float4*)s_wk)[q + 4 * i];
    }
    const float bqs = s_bsum[0];
    const float bks = s_bsum[1];

    // Slot geometry is su-invariant: slot = it*8+g
    int pr_[3], row_[3];
#pragma unroll
    for (int it = 0; it < 3; it++) {
        const int slot = it * 8 + g;
        pr_[it]  = slot / 12;
        row_[it] = slot - pr_[it] * 12;
    }

    const float4* __restrict__ x4 = (const float4*)x;
    const int warpPairBase = (blockIdx.x * WARPS + wid) * PAIRS_PER_WARP;

    float4 v[2][3][4];

    // Prologue: load su=0 into bank 0
#pragma unroll
    for (int it = 0; it < 3; it++) {
        const int gp = warpPairBase + pr_[it];
        const int b  = gp >> 9;
        const int n  = gp & 511;
        const size_t rowbase = ((size_t)(b * T_ + row_[it]) * N_ + n) * 16;
        v[0][it][0] = x4[rowbase + q];
        v[0][it][1] = x4[rowbase + q + 4];
        v[0][it][2] = x4[rowbase + q + 8];
        v[0][it][3] = x4[rowbase + q + 12];
    }

#pragma unroll
    for (int su = 0; su < NSU; su++) {
        const int cb = su & 1;
        const int nb = cb ^ 1;

        // ---- Issue next su's 12 loads (overlap with reduce below) ----
        if (su < NSU - 1) {
            const int pbaseN = warpPairBase + 2 * (su + 1);
#pragma unroll
            for (int it = 0; it < 3; it++) {
                const int gp = pbaseN + pr_[it];
                const int b  = gp >> 9;
                const int n  = gp & 511;
                const size_t rowbase = ((size_t)(b * T_ + row_[it]) * N_ + n) * 16;
                v[nb][it][0] = x4[rowbase + q];
                v[nb][it][1] = x4[rowbase + q + 4];
                v[nb][it][2] = x4[rowbase + q + 8];
                v[nb][it][3] = x4[rowbase + q + 12];
            }
        }

        // ---- Reduce current su: 3 independent chains ----
#pragma unroll
        for (int it = 0; it < 3; it++) {
            const float4* vv = v[cb][it];
            float aq = vv[0].x * wq4r[0].x + vv[0].y * wq4r[0].y + vv[0].z * wq4r[0].z + vv[0].w * wq4r[0].w
                     + vv[1].x * wq4r[1].x + vv[1].y * wq4r[1].y + vv[1].z * wq4r[1].z + vv[1].w * wq4r[1].w
                     + vv[2].x * wq4r[2].x + vv[2].y * wq4r[2].y + vv[2].z * wq4r[2].z + vv[2].w * wq4r[2].w
                     + vv[3].x * wq4r[3].x + vv[3].y * wq4r[3].y + vv[3].z * wq4r[3].z + vv[3].w * wq4r[3].w;
            float ak = vv[0].x * wk4r[0].x + vv[0].y * wk4r[0].y + vv[0].z * wk4r[0].z + vv[0].w * wk4r[0].w
                     + vv[1].x * wk4r[1].x + vv[1].y * wk4r[1].y + vv[1].z * wk4r[1].z + vv[1].w * wk4r[1].w
                     + vv[2].x * wk4r[2].x + vv[2].y * wk4r[2].y + vv[2].z * wk4r[2].z + vv[2].w * wk4r[2].w
                     + vv[3].x * wk4r[3].x + vv[3].y * wk4r[3].y + vv[3].z * wk4r[3].z + vv[3].w * wk4r[3].w;

            // 4-lane reduction, 3 shuffles, depth 2
            const float aq2 = aq + __shfl_xor_sync(0xffffffffu, aq, 2);
            const float ak2 = ak + __shfl_xor_sync(0xffffffffu, ak, 2);
            const float vsel = (q & 1) ? aq2 : ak2;
            const float toth = __shfl_xor_sync(0xffffffffu, vsel, 1);

            const int e = wid * PAIRS_PER_WARP + 2 * su + pr_[it];   // 0..63
            if (q == 0) s_q[e * T_ + row_[it]] = aq2 + toth + bqs;
            else if (q == 1) s_k[e * T_ + row_[it]] = ak2 + toth + bks;
        }
    }
    __syncthreads();

    // ---- Block-local 12x12 gram over the 64 staged (b,n) pairs ----
    if (tid < 144) {
        const int i = tid / 12;
        const int j = tid - i * 12;
        float acc = 0.f;
#pragma unroll 8
        for (int e = 0; e < PAIRS_PER_BLOCK; e++)
            acc += s_q[e * T_ + i] * s_k[e * T_ + j];
        g_partial[blockIdx.x * 144 + tid] = acc;
    }

    // ---- Last-block ticket ----
    __threadfence();          // publish g_partial
    __syncthreads();
    if (tid == 0) {
        unsigned int old = atomicAdd(&g_ticket, 1u);
        s_last = (old == BLOCKS - 1u);
    }
    __syncthreads();
    if (!s_last) return;

    __threadfence();          // acquire all blocks' g_partial

    // ---- Final reduction: 256 partials -> 12x12 scores ----
    // g_partial viewed as [BLOCKS][36] float4; 252 threads = 7 slices x 36 groups.
    if (tid < 252) {
        const int s  = tid / 36;
        const int g4 = tid - s * 36;
        const float4* gp4 = (const float4*)g_partial;
        float4 acc = make_float4(0.f, 0.f, 0.f, 0.f);
#pragma unroll 4
        for (int e = s; e < BLOCKS; e += 7) {
            const float4 vv = gp4[e * 36 + g4];
            acc.x += vv.x; acc.y += vv.y; acc.z += vv.z; acc.w += vv.w;
        }
        s_part[s][g4 * 4 + 0] = acc.x;
        s_part[s][g4 * 4 + 1] = acc.y;
        s_part[s][g4 * 4 + 2] = acc.z;
        s_part[s][g4 * 4 + 3] = acc.w;
    }
    __syncthreads();

    if (tid < 144) {
        float a = 0.f;
#pragma unroll
        for (int s = 0; s < 7; s++) a += s_part[s][tid];
        // mean over (B, N, H) = / (32*512*64)
        s_score[tid] = a * (1.0f / 1048576.0f);
    }
    __syncthreads();

    if (tid == 0) g_ticket = 0u;   // reset for next graph replay

    // ---- Row-wise top-k (tau from out_size), jax tie-break = lowest index ----
    int tau;
    bool write_idx;
    if (out_n >= 2 * T_ && (out_n % (2 * T_)) == 0) {
        tau = out_n / (2 * T_);
        write_idx = true;
    } else {
        tau = out_n / T_;
        write_idx = false;
    }
    if (tau > T_) tau = T_;

    if (tid < T_) {
        const int i = tid;
        float v2[T_];
#pragma unroll
        for (int j = 0; j < T_; j++) v2[j] = s_score[i * 12 + j];
        unsigned usedmask = 0u;
        for (int r = 0; r < tau; r++) {
            float best = -CUDART_INF_F;
            int bj = 0;
#pragma unroll
            for (int j = 0; j < T_; j++) {
                bool ok = ((usedmask >> j) & 1u) == 0u && v2[j] > best;
                if (ok) { best = v2[j]; bj = j; }
            }
            usedmask |= (1u << bj);
            out[i * tau + r] = best;
            if (write_idx) out[T_ * tau + i * tau + r] = (float)bj;
        }
    }
}

extern "C" void kernel_launch(void* const* d_in, const int* in_sizes, int n_in,
                              void* d_out, int out_size)
{
    const float* x  = (const float*)d_in[0];
    const float* Wq = (const float*)d_in[1];
    const float* bq = (const float*)d_in[2];
    const float* Wk = (const float*)d_in[3];
    const float* bk = (const float*)d_in[4];
    (void)in_sizes; (void)n_in;

    fft_sel_fused<<<BLOCKS, THREADS>>>(x, Wq, bq, Wk, bk, (float*)d_out, out_size);
}

// round 12
// speedup vs baseline: 1.3203x; 1.3203x over previous
#include <cuda_runtime.h>
#include <math_constants.h>

// Shapes fixed by the problem
#define B_  32
#define T_  12
#define N_  512
#define F_  64
#define H_  64

#define BLOCKS 296             // 2 blocks per SM exactly (148 SMs)
#define THREADS 256
#define WARPS   8
#define TOTAL_WARPS (BLOCKS * WARPS)   // 2368
#define TOTAL_SU 8192          // 16384 pairs / 2 per su
#define N4WARPS (TOTAL_SU - 3 * TOTAL_WARPS)   // 1088 warps do 4 su, rest 3

// Per-block partial 12x12 gram matrices (overwritten every launch; no zeroing needed)
__device__ float g_partial[BLOCKS * 144];
// Ticket: zero at module load; last block resets to 0 each launch -> every
// graph replay starts clean (deterministic).
__device__ unsigned int g_ticket;

__global__ __launch_bounds__(THREADS, 2) void fft_sel_fused(
    const float* __restrict__ x,   // [B,T,N,F]
    const float* __restrict__ Wq,  // [F,H]
    const float* __restrict__ bq,  // [H]
    const float* __restrict__ Wk,  // [F,H]
    const float* __restrict__ bk,  // [H]
    float* __restrict__ out, int out_n)
{
    __shared__ float s_wq[F_], s_wk[F_];
    __shared__ float s_bsum[2];
    __shared__ float s_q[64 * T_];   // 64 staging slots x 12 t
    __shared__ float s_k[64 * T_];
    __shared__ float s_part[7][144];
    __shared__ float s_score[144];
    __shared__ bool  s_last;

    const int tid  = threadIdx.x;
    const int wid  = tid >> 5;
    const int lane = tid & 31;

    // ---- Zero staging slots (warps with 3 su leave 2 slots unused) ----
#pragma unroll
    for (int i = tid; i < 64 * T_; i += THREADS) { s_q[i] = 0.f; s_k[i] = 0.f; }

    // ---- Coalesced pre-sum of weights over H (exact FFT/irfft/mean-H collapse) ----
    {
#pragma unroll
        for (int r = 0; r < 8; r++) {
            const int f = wid * 8 + r;
            float aq = Wq[f * H_ + lane] + Wq[f * H_ + 32 + lane];
            float ak = Wk[f * H_ + lane] + Wk[f * H_ + 32 + lane];
#pragma unroll
            for (int s = 16; s >= 1; s >>= 1) {
                aq += __shfl_xor_sync(0xffffffffu, aq, s);
                ak += __shfl_xor_sync(0xffffffffu, ak, s);
            }
            if (lane == 0) { s_wq[f] = aq; s_wk[f] = ak; }
        }
        if (wid == 0) {
            float a = bq[lane] + bq[32 + lane];
#pragma unroll
            for (int s = 16; s >= 1; s >>= 1) a += __shfl_xor_sync(0xffffffffu, a, s);
            if (lane == 0) s_bsum[0] = a;
        } else if (wid == 1) {
            float a = bk[lane] + bk[32 + lane];
#pragma unroll
            for (int s = 16; s >= 1; s >>= 1) a += __shfl_xor_sync(0xffffffffu, a, s);
            if (lane == 0) s_bsum[1] = a;
        }
    }
    __syncthreads();

    // ---- 4-lane-group streaming, front-batched loads (R9 scheme) ----
    const int g = lane >> 2;
    const int q = lane & 3;

    float4 wq4r[4], wk4r[4];
#pragma unroll
    for (int i = 0; i < 4; i++) {
        wq4r[i] = ((const float4*)s_wq)[q + 4 * i];
        wk4r[i] = ((const float4*)s_wk)[q + 4 * i];
    }
    const float bqs = s_bsum[0];
    const float bks = s_bsum[1];

    // Slot geometry su-invariant: slot = it*8+g
    int pr_[3], row_[3];
#pragma unroll
    for (int it = 0; it < 3; it++) {
        const int slot = it * 8 + g;
        pr_[it]  = slot / 12;
        row_[it] = slot - pr_[it] * 12;
    }

    // Balanced work split at su granularity: first N4WARPS warps take 4 su,
    // the rest take 3. Contiguous su chunks.
    const int gw = blockIdx.x * WARPS + wid;
    int suStart, suCnt;
    if (gw < N4WARPS) { suStart = gw * 4;                       suCnt = 4; }
    else              { suStart = N4WARPS * 4 + (gw - N4WARPS) * 3; suCnt = 3; }

    const float4* __restrict__ x4 = (const float4*)x;

#pragma unroll
    for (int lsu = 0; lsu < 4; lsu++) {
        if (lsu < suCnt) {
            const int su = suStart + lsu;
            const int pbase = 2 * su;          // global pair base

            float4 v[3][4];
            // ---- Load phase: 12 independent LDG.128 ----
#pragma unroll
            for (int it = 0; it < 3; it++) {
                const int gp = pbase + pr_[it];
                const int b  = gp >> 9;
                const int n  = gp & 511;
                const size_t rowbase = ((size_t)(b * T_ + row_[it]) * N_ + n) * 16;
                v[it][0] = x4[rowbase + q];
                v[it][1] = x4[rowbase + q + 4];
                v[it][2] = x4[rowbase + q + 8];
                v[it][3] = x4[rowbase + q + 12];
            }

            // ---- Reduce phase: 3 independent chains ----
#pragma unroll
            for (int it = 0; it < 3; it++) {
                const float4* vv = v[it];
                float aq = vv[0].x * wq4r[0].x + vv[0].y * wq4r[0].y + vv[0].z * wq4r[0].z + vv[0].w * wq4r[0].w
                         + vv[1].x * wq4r[1].x + vv[1].y * wq4r[1].y + vv[1].z * wq4r[1].z + vv[1].w * wq4r[1].w
                         + vv[2].x * wq4r[2].x + vv[2].y * wq4r[2].y + vv[2].z * wq4r[2].z + vv[2].w * wq4r[2].w
                         + vv[3].x * wq4r[3].x + vv[3].y * wq4r[3].y + vv[3].z * wq4r[3].z + vv[3].w * wq4r[3].w;
                float ak = vv[0].x * wk4r[0].x + vv[0].y * wk4r[0].y + vv[0].z * wk4r[0].z + vv[0].w * wk4r[0].w
                         + vv[1].x * wk4r[1].x + vv[1].y * wk4r[1].y + vv[1].z * wk4r[1].z + vv[1].w * wk4r[1].w
                         + vv[2].x * wk4r[2].x + vv[2].y * wk4r[2].y + vv[2].z * wk4r[2].z + vv[2].w * wk4r[2].w
                         + vv[3].x * wk4r[3].x + vv[3].y * wk4r[3].y + vv[3].z * wk4r[3].z + vv[3].w * wk4r[3].w;

                // 4-lane reduction, 3 shuffles, depth 2
                const float aq2 = aq + __shfl_xor_sync(0xffffffffu, aq, 2);
                const float ak2 = ak + __shfl_xor_sync(0xffffffffu, ak, 2);
                const float vsel = (q & 1) ? aq2 : ak2;
                const float toth = __shfl_xor_sync(0xffffffffu, vsel, 1);

                const int e = wid * 8 + 2 * lsu + pr_[it];   // 0..63 staging slot
                if (q == 0) s_q[e * T_ + row_[it]] = aq2 + toth + bqs;
                else if (q == 1) s_k[e * T_ + row_[it]] = ak2 + toth + bks;
            }
        }
    }
    __syncthreads();

    // ---- Block-local 12x12 gram over the 64 staging slots ----
    if (tid < 144) {
        const int i = tid / 12;
        const int j = tid - i * 12;
        float acc = 0.f;
#pragma unroll 8
        for (int e = 0; e < 64; e++)
            acc += s_q[e * T_ + i] * s_k[e * T_ + j];
        g_partial[blockIdx.x * 144 + tid] = acc;
    }

    // ---- Last-block ticket ----
    __threadfence();          // publish g_partial
    __syncthreads();
    if (tid == 0) {
        unsigned int old = atomicAdd(&g_ticket, 1u);
        s_last = (old == BLOCKS - 1u);
    }
    __syncthreads();
    if (!s_last) return;

    __threadfence();          // acquire all blocks' g_partial

    // ---- Final reduction: 296 partials -> 12x12 scores ----
    // g_partial viewed as [BLOCKS][36] float4; 252 threads = 7 slices x 36 groups.
    if (tid < 252) {
        const int s  = tid / 36;
        const int g4 = tid - s * 36;
        const float4* gp4 = (const float4*)g_partial;
        float4 acc = make_float4(0.f, 0.f, 0.f, 0.f);
#pragma unroll 4
        for (int e = s; e < BLOCKS; e += 7) {
            const float4 vv = gp4[e * 36 + g4];
            acc.x += vv.x; acc.y += vv.y; acc.z += vv.z; acc.w += vv.w;
        }
        s_part[s][g4 * 4 + 0] = acc.x;
        s_part[s][g4 * 4 + 1] = acc.y;
        s_part[s][g4 * 4 + 2] = acc.z;
        s_part[s][g4 * 4 + 3] = acc.w;
    }
    __syncthreads();

    if (tid < 144) {
        float a = 0.f;
#pragma unroll
        for (int s = 0; s < 7; s++) a += s_part[s][tid];
        // mean over (B, N, H) = / (32*512*64)
        s_score[tid] = a * (1.0f / 1048576.0f);
    }
    __syncthreads();

    if (tid == 0) g_ticket = 0u;   // reset for next graph replay

    // ---- Row-wise top-k (tau from out_size), jax tie-break = lowest index ----
    int tau;
    bool write_idx;
    if (out_n >= 2 * T_ && (out_n % (2 * T_)) == 0) {
        tau = out_n / (2 * T_);
        write_idx = true;
    } else {
        tau = out_n / T_;
        write_idx = false;
    }
    if (tau > T_) tau = T_;

    if (tid < T_) {
        const int i = tid;
        float v2[T_];
#pragma unroll
        for (int j = 0; j < T_; j++) v2[j] = s_score[i * 12 + j];
        unsigned usedmask = 0u;
        for (int r = 0; r < tau; r++) {
            float best = -CUDART_INF_F;
            int bj = 0;
#pragma unroll
            for (int j = 0; j < T_; j++) {
                bool ok = ((usedmask >> j) & 1u) == 0u && v2[j] > best;
                if (ok) { best = v2[j]; bj = j; }
            }
            usedmask |= (1u << bj);
            out[i * tau + r] = best;
            if (write_idx) out[T_ * tau + i * tau + r] = (float)bj;
        }
    }
}

extern "C" void kernel_launch(void* const* d_in, const int* in_sizes, int n_in,
                              void* d_out, int out_size)
{
    const float* x  = (const float*)d_in[0];
    const float* Wq = (const float*)d_in[1];
    const float* bq = (const float*)d_in[2];
    const float* Wk = (const float*)d_in[3];
    const float* bk = (const float*)d_in[4];
    (void)in_sizes; (void)n_in;

    fft_sel_fused<<<BLOCKS, THREADS>>>(x, Wq, bq, Wk, bk, (float*)d_out, out_size);
}

// round 13
// speedup vs baseline: 1.3228x; 1.0019x over previous
#include <cuda_runtime.h>
#include <math_constants.h>

// Shapes fixed by the problem
#define B_  32
#define T_  12
#define N_  512
#define F_  64
#define H_  64

#define BLOCKS 256
#define THREADS 256
#define WARPS   8
#define PAIRS_PER_WARP  8      // 256 * 8 * 8 = 16384 = B*N
#define PAIRS_PER_BLOCK 64
#define NSU (PAIRS_PER_WARP / 2)   // 4 super-iters, 2 pairs each

// Per-block partial 12x12 gram matrices (overwritten every launch; no zeroing needed)
__device__ float g_partial[BLOCKS * 144];
// Ticket: zero at module load; last block resets to 0 each launch -> every
// graph replay starts clean (deterministic).
__device__ unsigned int g_ticket;

__global__ __launch_bounds__(THREADS) void fft_sel_fused(
    const float* __restrict__ x,   // [B,T,N,F]
    const float* __restrict__ Wq,  // [F,H]
    const float* __restrict__ bq,  // [H]
    const float* __restrict__ Wk,  // [F,H]
    const float* __restrict__ bk,  // [H]
    float* __restrict__ out, int out_n)
{
    __shared__ float s_wq[F_], s_wk[F_];
    __shared__ float s_bsum[2];
    __shared__ float s_q[PAIRS_PER_BLOCK * T_];   // 64 pairs x 12 t
    __shared__ float s_k[PAIRS_PER_BLOCK * T_];
    __shared__ float s_part[7][144];
    __shared__ float s_score[144];
    __shared__ bool  s_last;

    const int tid  = threadIdx.x;
    const int wid  = tid >> 5;
    const int lane = tid & 31;

    // ---- Coalesced pre-sum of weights over H (exact FFT/irfft/mean-H collapse) ----
    {
#pragma unroll
        for (int r = 0; r < 8; r++) {
            const int f = wid * 8 + r;
            float aq = Wq[f * H_ + lane] + Wq[f * H_ + 32 + lane];
            float ak = Wk[f * H_ + lane] + Wk[f * H_ + 32 + lane];
#pragma unroll
            for (int s = 16; s >= 1; s >>= 1) {
                aq += __shfl_xor_sync(0xffffffffu, aq, s);
                ak += __shfl_xor_sync(0xffffffffu, ak, s);
            }
            if (lane == 0) { s_wq[f] = aq; s_wk[f] = ak; }
        }
        if (wid == 0) {
            float a = bq[lane] + bq[32 + lane];
#pragma unroll
            for (int s = 16; s >= 1; s >>= 1) a += __shfl_xor_sync(0xffffffffu, a, s);
            if (lane == 0) s_bsum[0] = a;
        } else if (wid == 1) {
            float a = bk[lane] + bk[32 + lane];
#pragma unroll
            for (int s = 16; s >= 1; s >>= 1) a += __shfl_xor_sync(0xffffffffu, a, s);
            if (lane == 0) s_bsum[1] = a;
        }
    }
    __syncthreads();

    // ---- 4-lane-group streaming, front-batched loads + L1 prefetch of next su ----
    const int g = lane >> 2;
    const int q = lane & 3;

    float4 wq4r[4], wk4r[4];
#pragma unroll
    for (int i = 0; i < 4; i++) {
        wq4r[i] = ((const float4*)s_wq)[q + 4 * i];
        wk4r[i] = ((const float4*)s_wk)[q + 4 * i];
    }
    const float bqs = s_bsum[0];
    const float bks = s_bsum[1];

    // Slot geometry is su-invariant: slot = it*8+g
    int pr_[3], row_[3];
#pragma unroll
    for (int it = 0; it < 3; it++) {
        const int slot = it * 8 + g;
        pr_[it]  = slot / 12;
        row_[it] = slot - pr_[it] * 12;
    }

    const float4* __restrict__ x4 = (const float4*)x;
    const int warpPairBase = (blockIdx.x * WARPS + wid) * PAIRS_PER_WARP;

#pragma unroll
    for (int su = 0; su < NSU; su++) {
        const int pbase = warpPairBase + 2 * su;

        float4 v[3][4];

        // ---- Load phase: 12 independent LDG.128 ----
#pragma unroll
        for (int it = 0; it < 3; it++) {
            const int gp = pbase + pr_[it];
            const int b  = gp >> 9;
            const int n  = gp & 511;
            const size_t rowbase = ((size_t)(b * T_ + row_[it]) * N_ + n) * 16;
            v[it][0] = x4[rowbase + q];
            v[it][1] = x4[rowbase + q + 4];
            v[it][2] = x4[rowbase + q + 8];
            v[it][3] = x4[rowbase + q + 12];
        }

        // ---- Prefetch next su's rows into L1 (overlaps reduce below) ----
        // Lane address rowbase_next + q*64B: q=0..3 covers byte offsets
        // 0/64/128/192 -> both 128B lines of each group's 256B row.
        if (su < NSU - 1) {
#pragma unroll
            for (int it = 0; it < 3; it++) {
                const int gpN = pbase + 2 + pr_[it];
                if (gpN < B_ * N_) {
                    const int bN = gpN >> 9;
                    const int nN = gpN & 511;
                    const size_t rbN = ((size_t)(bN * T_ + row_[it]) * N_ + nN) * 16;
                    const float* pf = (const float*)(x4 + rbN) + q * 16;
                    asm volatile("prefetch.global.L1 [%0];" :: "l"(pf));
                }
            }
        }

        // ---- Reduce phase: 3 independent chains (latencies overlap) ----
#pragma unroll
        for (int it = 0; it < 3; it++) {
            const float4* vv = v[it];
            float aq = vv[0].x * wq4r[0].x + vv[0].y * wq4r[0].y + vv[0].z * wq4r[0].z + vv[0].w * wq4r[0].w
                     + vv[1].x * wq4r[1].x + vv[1].y * wq4r[1].y + vv[1].z * wq4r[1].z + vv[1].w * wq4r[1].w
                     + vv[2].x * wq4r[2].x + vv[2].y * wq4r[2].y + vv[2].z * wq4r[2].z + vv[2].w * wq4r[2].w
                     + vv[3].x * wq4r[3].x + vv[3].y * wq4r[3].y + vv[3].z * wq4r[3].z + vv[3].w * wq4r[3].w;
            float ak = vv[0].x * wk4r[0].x + vv[0].y * wk4r[0].y + vv[0].z * wk4r[0].z + vv[0].w * wk4r[0].w
                     + vv[1].x * wk4r[1].x + vv[1].y * wk4r[1].y + vv[1].z * wk4r[1].z + vv[1].w * wk4r[1].w
                     + vv[2].x * wk4r[2].x + vv[2].y * wk4r[2].y + vv[2].z * wk4r[2].z + vv[2].w * wk4r[2].w
                     + vv[3].x * wk4r[3].x + vv[3].y * wk4r[3].y + vv[3].z * wk4r[3].z + vv[3].w * wk4r[3].w;

            // 4-lane reduction, 3 shuffles, depth 2
            const float aq2 = aq + __shfl_xor_sync(0xffffffffu, aq, 2);
            const float ak2 = ak + __shfl_xor_sync(0xffffffffu, ak, 2);
            const float vsel = (q & 1) ? aq2 : ak2;
            const float toth = __shfl_xor_sync(0xffffffffu, vsel, 1);

            const int e = wid * PAIRS_PER_WARP + 2 * su + pr_[it];   // 0..63
            if (q == 0) s_q[e * T_ + row_[it]] = aq2 + toth + bqs;
            else if (q == 1) s_k[e * T_ + row_[it]] = ak2 + toth + bks;
        }
    }
    __syncthreads();

    // ---- Block-local 12x12 gram over the 64 staged (b,n) pairs ----
    if (tid < 144) {
        const int i = tid / 12;
        const int j = tid - i * 12;
        float acc = 0.f;
#pragma unroll 8
        for (int e = 0; e < PAIRS_PER_BLOCK; e++)
            acc += s_q[e * T_ + i] * s_k[e * T_ + j];
        g_partial[blockIdx.x * 144 + tid] = acc;
    }

    // ---- Last-block ticket ----
    __threadfence();          // publish g_partial
    __syncthreads();
    if (tid == 0) {
        unsigned int old = atomicAdd(&g_ticket, 1u);
        s_last = (old == BLOCKS - 1u);
    }
    __syncthreads();
    if (!s_last) return;

    __threadfence();          // acquire all blocks' g_partial

    // ---- Final reduction: 256 partials -> 12x12 scores ----
    // g_partial viewed as [BLOCKS][36] float4; 252 threads = 7 slices x 36 groups.
    if (tid < 252) {
        const int s  = tid / 36;
        const int g4 = tid - s * 36;
        const float4* gp4 = (const float4*)g_partial;
        float4 acc = make_float4(0.f, 0.f, 0.f, 0.f);
#pragma unroll 4
        for (int e = s; e < BLOCKS; e += 7) {
            const float4 vv = gp4[e * 36 + g4];
            acc.x += vv.x; acc.y += vv.y; acc.z += vv.z; acc.w += vv.w;
        }
        s_part[s][g4 * 4 + 0] = acc.x;
        s_part[s][g4 * 4 + 1] = acc.y;
        s_part[s][g4 * 4 + 2] = acc.z;
        s_part[s][g4 * 4 + 3] = acc.w;
    }
    __syncthreads();

    if (tid < 144) {
        float a = 0.f;
#pragma unroll
        for (int s = 0; s < 7; s++) a += s_part[s][tid];
        // mean over (B, N, H) = / (32*512*64)
        s_score[tid] = a * (1.0f / 1048576.0f);
    }
    __syncthreads();

    if (tid == 0) g_ticket = 0u;   // reset for next graph replay

    // ---- Row-wise top-k (tau from out_size), jax tie-break = lowest index ----
    int tau;
    bool write_idx;
    if (out_n >= 2 * T_ && (out_n % (2 * T_)) == 0) {
        tau = out_n / (2 * T_);
        write_idx = true;
    } else {
        tau = out_n / T_;
        write_idx = false;
    }
    if (tau > T_) tau = T_;

    if (tid < T_) {
        const int i = tid;
        float v2[T_];
#pragma unroll
        for (int j = 0; j < T_; j++) v2[j] = s_score[i * 12 + j];
        unsigned usedmask = 0u;
        for (int r = 0; r < tau; r++) {
            float best = -CUDART_INF_F;
            int bj = 0;
#pragma unroll
            for (int j = 0; j < T_; j++) {
                bool ok = ((usedmask >> j) & 1u) == 0u && v2[j] > best;
                if (ok) { best = v2[j]; bj = j; }
            }
            usedmask |= (1u << bj);
            out[i * tau + r] = best;
            if (write_idx) out[T_ * tau + i * tau + r] = (float)bj;
        }
    }
}

extern "C" void kernel_launch(void* const* d_in, const int* in_sizes, int n_in,
                              void* d_out, int out_size)
{
    const float* x  = (const float*)d_in[0];
    const float* Wq = (const float*)d_in[1];
    const float* bq = (const float*)d_in[2];
    const float* Wk = (const float*)d_in[3];
    const float* bk = (const float*)d_in[4];
    (void)in_sizes; (void)n_in;

    fft_sel_fused<<<BLOCKS, THREADS>>>(x, Wq, bq, Wk, bk, (float*)d_out, out_size);
}

// round 16
// speedup vs baseline: 1.5313x; 1.1577x over previous
#include <cuda_runtime.h>
#include <math_constants.h>

// Shapes fixed by the problem
#define B_  32
#define T_  12
#define N_  512
#define F_  64
#define H_  64

#define BLOCKS 256
#define THREADS 256
#define WARPS   8
#define PAIRS_PER_WARP  8      // 256 * 8 * 8 = 16384 = B*N
#define PAIRS_PER_BLOCK 64
#define NSU (PAIRS_PER_WARP / 2)   // 4 super-iters, 2 pairs each

// Global accumulator for the 12x12 gram (REDG atomic adds from all blocks).
// Zero at module load; last block resets to 0 each launch.
__device__ float g_score[144];
// Ticket: zero at module load; last block resets to 0 each launch.
__device__ unsigned int g_ticket;

__global__ __launch_bounds__(THREADS) void fft_sel_fused(
    const float* __restrict__ x,   // [B,T,N,F]
    const float* __restrict__ Wq,  // [F,H]
    const float* __restrict__ bq,  // [H]
    const float* __restrict__ Wk,  // [F,H]
    const float* __restrict__ bk,  // [H]
    float* __restrict__ out, int out_n)
{
    __shared__ float s_wq[F_], s_wk[F_];
    __shared__ float s_bsum[2];
    __shared__ float s_q[PAIRS_PER_BLOCK * T_];   // 64 pairs x 12 t
    __shared__ float s_k[PAIRS_PER_BLOCK * T_];
    __shared__ float s_score[144];
    __shared__ bool  s_last;

    const int tid  = threadIdx.x;
    const int wid  = tid >> 5;
    const int lane = tid & 31;

    // ---- Coalesced pre-sum of weights over H (exact FFT/irfft/mean-H collapse) ----
    {
#pragma unroll
        for (int r = 0; r < 8; r++) {
            const int f = wid * 8 + r;
            float aq = Wq[f * H_ + lane] + Wq[f * H_ + 32 + lane];
            float ak = Wk[f * H_ + lane] + Wk[f * H_ + 32 + lane];
#pragma unroll
            for (int s = 16; s >= 1; s >>= 1) {
                aq += __shfl_xor_sync(0xffffffffu, aq, s);
                ak += __shfl_xor_sync(0xffffffffu, ak, s);
            }
            if (lane == 0) { s_wq[f] = aq; s_wk[f] = ak; }
        }
        if (wid == 0) {
            float a = bq[lane] + bq[32 + lane];
#pragma unroll
            for (int s = 16; s >= 1; s >>= 1) a += __shfl_xor_sync(0xffffffffu, a, s);
            if (lane == 0) s_bsum[0] = a;
        } else if (wid == 1) {
            float a = bk[lane] + bk[32 + lane];
#pragma unroll
            for (int s = 16; s >= 1; s >>= 1) a += __shfl_xor_sync(0xffffffffu, a, s);
            if (lane == 0) s_bsum[1] = a;
        }
    }
    __syncthreads();

    // ---- 8-lane-group streaming: fully line-coalesced loads ----
    // Warp = 4 groups of 8 lanes. A group handles one (pair,row) slot per
    // slot-iter; lane q loads float4s q and q+8 of the 64-float row, so each
    // LDG.128 covers 4 FULL 128B lines (one per group) -> minimum wavefronts.
    const int g8 = lane >> 3;   // group 0..3
    const int q8 = lane & 7;    // lane within group

    const float4 wq0 = ((const float4*)s_wq)[q8];
    const float4 wq1 = ((const float4*)s_wq)[q8 + 8];
    const float4 wk0 = ((const float4*)s_wk)[q8];
    const float4 wk1 = ((const float4*)s_wk)[q8 + 8];
    const float bqs = s_bsum[0];
    const float bks = s_bsum[1];

    // Slot geometry su-invariant: slot = it*4 + g8, 6 slots cover 24 rows (2 pairs)
    int pr_[6], row_[6];
#pragma unroll
    for (int it = 0; it < 6; it++) {
        const int slot = it * 4 + g8;
        pr_[it]  = slot / 12;
        row_[it] = slot - pr_[it] * 12;
    }

    const float4* __restrict__ x4 = (const float4*)x;
    const int warpPairBase = (blockIdx.x * WARPS + wid) * PAIRS_PER_WARP;

#pragma unroll
    for (int su = 0; su < NSU; su++) {
        const int pbase = warpPairBase + 2 * su;

        float4 v0[6], v1[6];

        // ---- Load phase: 12 independent, fully-coalesced LDG.128 ----
#pragma unroll
        for (int it = 0; it < 6; it++) {
            const int gp = pbase + pr_[it];
            const int b  = gp >> 9;
            const int n  = gp & 511;
            const size_t rowbase = ((size_t)(b * T_ + row_[it]) * N_ + n) * 16;
            v0[it] = x4[rowbase + q8];
            v1[it] = x4[rowbase + 8 + q8];
        }

        // ---- Reduce phase: 6 independent chains ----
#pragma unroll
        for (int it = 0; it < 6; it++) {
            float aq = v0[it].x * wq0.x + v0[it].y * wq0.y + v0[it].z * wq0.z + v0[it].w * wq0.w
                     + v1[it].x * wq1.x + v1[it].y * wq1.y + v1[it].z * wq1.z + v1[it].w * wq1.w;
            float ak = v0[it].x * wk0.x + v0[it].y * wk0.y + v0[it].z * wk0.z + v0[it].w * wk0.w
                     + v1[it].x * wk1.x + v1[it].y * wk1.y + v1[it].z * wk1.z + v1[it].w * wk1.w;

            // 8-lane reduction (within octet): xor4, xor2, then cross-pack xor1
            float t1 = aq + __shfl_xor_sync(0xffffffffu, aq, 4);
            const float aq2 = t1 + __shfl_xor_sync(0xffffffffu, t1, 2);
            float t2 = ak + __shfl_xor_sync(0xffffffffu, ak, 4);
            const float ak2 = t2 + __shfl_xor_sync(0xffffffffu, t2, 2);
            const float vsel = (q8 & 1) ? aq2 : ak2;
            const float toth = __shfl_xor_sync(0xffffffffu, vsel, 1);

            const int e = wid * PAIRS_PER_WARP + 2 * su + pr_[it];   // 0..63
            if (q8 == 0) s_q[e * T_ + row_[it]] = aq2 + toth + bqs;
            else if (q8 == 1) s_k[e * T_ + row_[it]] = ak2 + toth + bks;
        }
    }
    __syncthreads();

    // ---- Block-local 12x12 gram over the 64 staged (b,n) pairs,
    //      accumulated globally via REDG (no per-block partial arrays) ----
    if (tid < 144) {
        const int i = tid / 12;
        const int j = tid - i * 12;
        float acc = 0.f;
#pragma unroll 8
        for (int e = 0; e < PAIRS_PER_BLOCK; e++)
            acc += s_q[e * T_ + i] * s_k[e * T_ + j];
        atomicAdd(&g_score[tid], acc);
    }

    // ---- Last-block ticket ----
    __threadfence();          // publish g_score adds
    __syncthreads();
    if (tid == 0) {
        unsigned int old = atomicAdd(&g_ticket, 1u);
        s_last = (old == BLOCKS - 1u);
    }
    __syncthreads();
    if (!s_last) return;

    __threadfence();          // acquire all blocks' adds

    // ---- Finalize: scale, reset accumulator for next graph replay ----
    if (tid < 144) {
        const float a = g_score[tid];
        // mean over (B, N, H) = / (32*512*64)
        s_score[tid] = a * (1.0f / 1048576.0f);
        g_score[tid] = 0.f;
    }
    __syncthreads();

    if (tid == 0) g_ticket = 0u;   // reset for next graph replay

    // ---- Row-wise top-k (tau from out_size), jax tie-break = lowest index ----
    int tau;
    bool write_idx;
    if (out_n >= 2 * T_ && (out_n % (2 * T_)) == 0) {
        tau = out_n / (2 * T_);
        write_idx = true;
    } else {
        tau = out_n / T_;
        write_idx = false;
    }
    if (tau > T_) tau = T_;

    if (tid < T_) {
        const int i = tid;
        float v2[T_];
#pragma unroll
        for (int j = 0; j < T_; j++) v2[j] = s_score[i * 12 + j];
        unsigned usedmask = 0u;
        for (int r = 0; r < tau; r++) {
            float best = -CUDART_INF_F;
            int bj = 0;
#pragma unroll
            for (int j = 0; j < T_; j++) {
                bool ok = ((usedmask >> j) & 1u) == 0u && v2[j] > best;
                if (ok) { best = v2[j]; bj = j; }
            }
            usedmask |= (1u << bj);
            out[i * tau + r] = best;
            if (write_idx) out[T_ * tau + i * tau + r] = (float)bj;
        }
    }
}

extern "C" void kernel_launch(void* const* d_in, const int* in_sizes, int n_in,
                              void* d_out, int out_size)
{
    const float* x  = (const float*)d_in[0];
    const float* Wq = (const float*)d_in[1];
    const float* bq = (const float*)d_in[2];
    const float* Wk = (const float*)d_in[3];
    const float* bk = (const float*)d_in[4];
    (void)in_sizes; (void)n_in;

    fft_sel_fused<<<BLOCKS, THREADS>>>(x, Wq, bq, Wk, bk, (float*)d_out, out_size);
}